// round 16
// baseline (speedup 1.0000x reference)
#include <cuda_runtime.h>
#include <cstdint>

#define NUM_T   128
#define DIM     1024
#define D4      (DIM / 4)
#define NC      512
#define TOPK    8
#define VPC     256
#define VOCAB   131072
#define TILE    4
#define RPC     32          // rows per chunk in logits kernel
#define NCHUNK  (VPC / RPC) // 8

// scratch (__device__ globals; no allocations allowed)
__device__ float g_scores[NUM_T * NC];
__device__ int   g_topk[NUM_T * TOPK];

// ---------------------------------------------------------------------------
// Centroid scores FUSED with output fill.
// block = 4 tokens x 8 centroids (warp per centroid); grid (32,64) = 2048.
// scores is latency-bound with DRAM at 1.9% -> the 64 MiB -FLT_MAX fill
// rides along on the idle store path (fire-and-forget, no dependencies).
// ---------------------------------------------------------------------------
__global__ void scores_fill_kernel(const float* __restrict__ H,
                                   const float* __restrict__ C,
                                   float4* __restrict__ out, int n4) {
    __shared__ float4 Hs4[4 * D4];   // 16 KB

    const int tid  = threadIdx.x;
    const int lane = tid & 31;
    const int warp = tid >> 5;
    const int t0   = blockIdx.x * 4;
    const int c    = blockIdx.y * 8 + warp;

    const float4* H4 = (const float4*)H;
    for (int i = tid; i < 4 * D4; i += 256)
        Hs4[i] = H4[t0 * D4 + i];
    __syncthreads();

    const float4* C4 = (const float4*)C;
    float a0 = 0.f, a1 = 0.f, a2 = 0.f, a3 = 0.f;
    #pragma unroll 2
    for (int j = 0; j < DIM / 128; j++) {
        const float4 cv = C4[(size_t)c * D4 + lane + 32 * j];
        const float4 h0 = Hs4[0 * D4 + lane + 32 * j];
        const float4 h1 = Hs4[1 * D4 + lane + 32 * j];
        const float4 h2 = Hs4[2 * D4 + lane + 32 * j];
        const float4 h3 = Hs4[3 * D4 + lane + 32 * j];
        a0 += cv.x * h0.x + cv.y * h0.y + cv.z * h0.z + cv.w * h0.w;
        a1 += cv.x * h1.x + cv.y * h1.y + cv.z * h1.z + cv.w * h1.w;
        a2 += cv.x * h2.x + cv.y * h2.y + cv.z * h2.z + cv.w * h2.w;
        a3 += cv.x * h3.x + cv.y * h3.y + cv.z * h3.z + cv.w * h3.w;
    }
    #pragma unroll
    for (int s = 16; s; s >>= 1) {
        a0 += __shfl_xor_sync(0xffffffffu, a0, s);
        a1 += __shfl_xor_sync(0xffffffffu, a1, s);
        a2 += __shfl_xor_sync(0xffffffffu, a2, s);
        a3 += __shfl_xor_sync(0xffffffffu, a3, s);
    }
    if (lane == 0) {
        g_scores[(t0 + 0) * NC + c] = a0;
        g_scores[(t0 + 1) * NC + c] = a1;
        g_scores[(t0 + 2) * NC + c] = a2;
        g_scores[(t0 + 3) * NC + c] = a3;
    }

    // grid-stride fill of the whole output with -FLT_MAX (streaming stores)
    const float v = __int_as_float(0xff7fffff);
    const float4 f = make_float4(v, v, v, v);
    const int blk    = blockIdx.y * gridDim.x + blockIdx.x;
    const int stride = gridDim.x * gridDim.y * 256;
    for (int i = blk * 256 + tid; i < n4; i += stride)
        __stcs(&out[i], f);
}

// ---------------------------------------------------------------------------
// Top-8 per token. 32 blocks x 128 threads, warp per token.
// Tie-break: lowest index (matches jax.lax.top_k).
// ---------------------------------------------------------------------------
__global__ void topk_kernel() {
    const int t    = blockIdx.x * 4 + (threadIdx.x >> 5);
    const int lane = threadIdx.x & 31;
    const float NEG_INF = __int_as_float(0xff800000);

    float sc[16];
    #pragma unroll
    for (int j = 0; j < 16; j++)
        sc[j] = g_scores[t * NC + lane * 16 + j];

    #pragma unroll
    for (int r = 0; r < TOPK; r++) {
        float bv = sc[0];
        int   bi = lane * 16;
        #pragma unroll
        for (int j = 1; j < 16; j++)
            if (sc[j] > bv) { bv = sc[j]; bi = lane * 16 + j; }
        #pragma unroll
        for (int s = 16; s; s >>= 1) {
            const float ov = __shfl_xor_sync(0xffffffffu, bv, s);
            const int   oi = __shfl_xor_sync(0xffffffffu, bi, s);
            if (ov > bv || (ov == bv && oi < bi)) { bv = ov; bi = oi; }
        }
        if (lane == (bi >> 4)) sc[bi & 15] = NEG_INF;
        if (lane == 0) g_topk[t * TOPK + r] = bi;
    }
}

// ---------------------------------------------------------------------------
// Centroid-major logits + scatter (fill already done by scores_fill).
// Block = (centroid c, 32-row chunk); grid = 4096, 256 threads.
// Token list rebuilt locally from g_topk (ballot). nt==0 blocks exit early
// (no W traffic for unselected centroids). W rows: __ldcs. Stores: __stcs.
// launch_bounds(256, 6) caps regs (~42) for >=6 blocks/SM at the DRAM wall.
// ---------------------------------------------------------------------------
__global__ void __launch_bounds__(256, 6) logits_kernel(
        const float* __restrict__ H,
        const float* __restrict__ W,
        const int* __restrict__ ord,
        float* __restrict__ out) {
    __shared__ float4 Hs[TILE][D4];    // 16 KB
    __shared__ int    toklist_s[NUM_T];
    __shared__ int    toks[TILE];
    __shared__ int    nt_s;

    const int c     = blockIdx.x >> 3;
    const int chunk = blockIdx.x & 7;
    const int r0    = chunk * RPC;
    const int tid   = threadIdx.x;
    const int lane  = tid & 31;
    const int warp  = tid >> 5;

    if (tid == 0) nt_s = 0;
    __syncthreads();

    if (tid < NUM_T) {
        bool sel = false;
        #pragma unroll
        for (int k = 0; k < TOPK; k++)
            sel |= (g_topk[tid * TOPK + k] == c);
        if (sel) toklist_s[atomicAdd(&nt_s, 1)] = tid;
    }
    __syncthreads();
    const int nt = nt_s;
    if (nt == 0) return;

    const float4* H4 = (const float4*)H;
    const float4* W4 = (const float4*)W;

    for (int base = 0; base < nt; base += TILE) {
        const int m = min(TILE, nt - base);
        if (tid < m) toks[tid] = toklist_s[base + tid];
        __syncthreads();
        for (int i = tid; i < m * D4; i += 256) {
            const int ti = i >> 8;
            const int e  = i & (D4 - 1);
            Hs[ti][e] = H4[(size_t)toks[ti] * D4 + e];
        }
        __syncthreads();

        int rvid = __ldg(&ord[c * VPC + r0 + warp]);
        #pragma unroll
        for (int rr = 0; rr < RPC; rr += 8) {
            const int cur_vid = rvid;
            if (rr + 8 < RPC)
                rvid = __ldg(&ord[c * VPC + r0 + rr + 8 + warp]);

            float s0 = 0.f, s1 = 0.f, s2 = 0.f, s3 = 0.f;
            #pragma unroll
            for (int half = 0; half < 2; half++) {
                float4 w[4];
                #pragma unroll
                for (int j = 0; j < 4; j++)
                    w[j] = __ldcs(&W4[(size_t)cur_vid * D4 + lane + 32 * (half * 4 + j)]);
                #pragma unroll
                for (int j = 0; j < 4; j++) {
                    const int e = lane + 32 * (half * 4 + j);
                    {
                        const float4 h = Hs[0][e];
                        s0 += w[j].x * h.x + w[j].y * h.y + w[j].z * h.z + w[j].w * h.w;
                    }
                    if (m > 1) {
                        const float4 h = Hs[1][e];
                        s1 += w[j].x * h.x + w[j].y * h.y + w[j].z * h.z + w[j].w * h.w;
                    }
                    if (m > 2) {
                        const float4 h = Hs[2][e];
                        s2 += w[j].x * h.x + w[j].y * h.y + w[j].z * h.z + w[j].w * h.w;
                    }
                    if (m > 3) {
                        const float4 h = Hs[3][e];
                        s3 += w[j].x * h.x + w[j].y * h.y + w[j].z * h.z + w[j].w * h.w;
                    }
                }
            }

            #pragma unroll
            for (int sft = 16; sft; sft >>= 1) {
                s0 += __shfl_xor_sync(0xffffffffu, s0, sft);
                s1 += __shfl_xor_sync(0xffffffffu, s1, sft);
                s2 += __shfl_xor_sync(0xffffffffu, s2, sft);
                s3 += __shfl_xor_sync(0xffffffffu, s3, sft);
            }
            if (lane == 0) {
                __stcs(&out[(size_t)toks[0] * VOCAB + cur_vid], s0);
                if (m > 1) __stcs(&out[(size_t)toks[1] * VOCAB + cur_vid], s1);
                if (m > 2) __stcs(&out[(size_t)toks[2] * VOCAB + cur_vid], s2);
                if (m > 3) __stcs(&out[(size_t)toks[3] * VOCAB + cur_vid], s3);
            }
        }
        __syncthreads();
    }
}

// ---------------------------------------------------------------------------
extern "C" void kernel_launch(void* const* d_in, const int* in_sizes, int n_in,
                              void* d_out, int out_size) {
    const float* H   = (const float*)d_in[0];   // (128, 1024)
    const float* W   = (const float*)d_in[1];   // (131072, 1024)
    const float* C   = (const float*)d_in[2];   // (512, 1024)
    const int*   ord = (const int*)d_in[3];     // (131072,)
    float* out = (float*)d_out;

    const int n4 = out_size / 4;
    scores_fill_kernel<<<dim3(NUM_T / 4, NC / 8), 256>>>(H, C, (float4*)out, n4);
    topk_kernel<<<NUM_T / 4, 128>>>();
    logits_kernel<<<NC * NCHUNK, 256>>>(H, W, ord, out);
}

// round 17
// speedup vs baseline: 1.1564x; 1.1564x over previous
#include <cuda_runtime.h>
#include <cstdint>

#define NUM_T   128
#define DIM     1024
#define D4      (DIM / 4)
#define NC      512
#define TOPK    8
#define VPC     256
#define VOCAB   131072
#define TILE    4
#define RPC     32          // rows per chunk in logits kernel
#define NCHUNK  (VPC / RPC) // 8

// scratch (__device__ globals; no allocations allowed)
__device__ float g_scores[NUM_T * NC];
__device__ int   g_topk[NUM_T * TOPK];

// ---------------------------------------------------------------------------
// Centroid scores FUSED with output fill.
// block = 4 tokens x 8 centroids (warp per centroid); grid (32,64) = 2048.
// scores is latency-bound with DRAM ~2% -> the 64 MiB -FLT_MAX fill rides
// on the idle store path (measured cost: +4.3us vs pure scores).
// ---------------------------------------------------------------------------
__global__ void scores_fill_kernel(const float* __restrict__ H,
                                   const float* __restrict__ C,
                                   float4* __restrict__ out, int n4) {
    __shared__ float4 Hs4[4 * D4];   // 16 KB

    const int tid  = threadIdx.x;
    const int lane = tid & 31;
    const int warp = tid >> 5;
    const int t0   = blockIdx.x * 4;
    const int c    = blockIdx.y * 8 + warp;

    const float4* H4 = (const float4*)H;
    for (int i = tid; i < 4 * D4; i += 256)
        Hs4[i] = H4[t0 * D4 + i];
    __syncthreads();

    const float4* C4 = (const float4*)C;
    float a0 = 0.f, a1 = 0.f, a2 = 0.f, a3 = 0.f;
    #pragma unroll 2
    for (int j = 0; j < DIM / 128; j++) {
        const float4 cv = C4[(size_t)c * D4 + lane + 32 * j];
        const float4 h0 = Hs4[0 * D4 + lane + 32 * j];
        const float4 h1 = Hs4[1 * D4 + lane + 32 * j];
        const float4 h2 = Hs4[2 * D4 + lane + 32 * j];
        const float4 h3 = Hs4[3 * D4 + lane + 32 * j];
        a0 += cv.x * h0.x + cv.y * h0.y + cv.z * h0.z + cv.w * h0.w;
        a1 += cv.x * h1.x + cv.y * h1.y + cv.z * h1.z + cv.w * h1.w;
        a2 += cv.x * h2.x + cv.y * h2.y + cv.z * h2.z + cv.w * h2.w;
        a3 += cv.x * h3.x + cv.y * h3.y + cv.z * h3.z + cv.w * h3.w;
    }
    #pragma unroll
    for (int s = 16; s; s >>= 1) {
        a0 += __shfl_xor_sync(0xffffffffu, a0, s);
        a1 += __shfl_xor_sync(0xffffffffu, a1, s);
        a2 += __shfl_xor_sync(0xffffffffu, a2, s);
        a3 += __shfl_xor_sync(0xffffffffu, a3, s);
    }
    if (lane == 0) {
        g_scores[(t0 + 0) * NC + c] = a0;
        g_scores[(t0 + 1) * NC + c] = a1;
        g_scores[(t0 + 2) * NC + c] = a2;
        g_scores[(t0 + 3) * NC + c] = a3;
    }

    // grid-stride fill of the whole output with -FLT_MAX (streaming stores)
    const float v = __int_as_float(0xff7fffff);
    const float4 f = make_float4(v, v, v, v);
    const int blk    = blockIdx.y * gridDim.x + blockIdx.x;
    const int stride = gridDim.x * gridDim.y * 256;
    for (int i = blk * 256 + tid; i < n4; i += stride)
        __stcs(&out[i], f);
}

// ---------------------------------------------------------------------------
// Top-8 per token. 32 blocks x 128 threads, warp per token.
// Tie-break: lowest index (matches jax.lax.top_k).
// ---------------------------------------------------------------------------
__global__ void topk_kernel() {
    const int t    = blockIdx.x * 4 + (threadIdx.x >> 5);
    const int lane = threadIdx.x & 31;
    const float NEG_INF = __int_as_float(0xff800000);

    float sc[16];
    #pragma unroll
    for (int j = 0; j < 16; j++)
        sc[j] = g_scores[t * NC + lane * 16 + j];

    #pragma unroll
    for (int r = 0; r < TOPK; r++) {
        float bv = sc[0];
        int   bi = lane * 16;
        #pragma unroll
        for (int j = 1; j < 16; j++)
            if (sc[j] > bv) { bv = sc[j]; bi = lane * 16 + j; }
        #pragma unroll
        for (int s = 16; s; s >>= 1) {
            const float ov = __shfl_xor_sync(0xffffffffu, bv, s);
            const int   oi = __shfl_xor_sync(0xffffffffu, bi, s);
            if (ov > bv || (ov == bv && oi < bi)) { bv = ov; bi = oi; }
        }
        if (lane == (bi >> 4)) sc[bi & 15] = NEG_INF;
        if (lane == 0) g_topk[t * TOPK + r] = bi;
    }
}

// ---------------------------------------------------------------------------
// Centroid-major logits + scatter (fill already done by scores_fill).
// Block = (centroid c, 32-row chunk); grid = 4096, 256 threads.
// NOTE: no min-blocks clause — R16's (256,6) forced a 42-reg cap and spilled
// the MAC loop to local memory, regressing the kernel. Natural regs ~50.
// ---------------------------------------------------------------------------
__global__ void __launch_bounds__(256) logits_kernel(
        const float* __restrict__ H,
        const float* __restrict__ W,
        const int* __restrict__ ord,
        float* __restrict__ out) {
    __shared__ float4 Hs[TILE][D4];    // 16 KB
    __shared__ int    toklist_s[NUM_T];
    __shared__ int    toks[TILE];
    __shared__ int    nt_s;

    const int c     = blockIdx.x >> 3;
    const int chunk = blockIdx.x & 7;
    const int r0    = chunk * RPC;
    const int tid   = threadIdx.x;
    const int lane  = tid & 31;
    const int warp  = tid >> 5;

    if (tid == 0) nt_s = 0;
    __syncthreads();

    if (tid < NUM_T) {
        bool sel = false;
        #pragma unroll
        for (int k = 0; k < TOPK; k++)
            sel |= (g_topk[tid * TOPK + k] == c);
        if (sel) toklist_s[atomicAdd(&nt_s, 1)] = tid;
    }
    __syncthreads();
    const int nt = nt_s;
    if (nt == 0) return;

    const float4* H4 = (const float4*)H;
    const float4* W4 = (const float4*)W;

    for (int base = 0; base < nt; base += TILE) {
        const int m = min(TILE, nt - base);
        if (tid < m) toks[tid] = toklist_s[base + tid];
        __syncthreads();
        for (int i = tid; i < m * D4; i += 256) {
            const int ti = i >> 8;
            const int e  = i & (D4 - 1);
            Hs[ti][e] = H4[(size_t)toks[ti] * D4 + e];
        }
        __syncthreads();

        int rvid = __ldg(&ord[c * VPC + r0 + warp]);
        #pragma unroll
        for (int rr = 0; rr < RPC; rr += 8) {
            const int cur_vid = rvid;
            if (rr + 8 < RPC)
                rvid = __ldg(&ord[c * VPC + r0 + rr + 8 + warp]);

            float s0 = 0.f, s1 = 0.f, s2 = 0.f, s3 = 0.f;
            #pragma unroll
            for (int half = 0; half < 2; half++) {
                float4 w[4];
                #pragma unroll
                for (int j = 0; j < 4; j++)
                    w[j] = __ldcs(&W4[(size_t)cur_vid * D4 + lane + 32 * (half * 4 + j)]);
                #pragma unroll
                for (int j = 0; j < 4; j++) {
                    const int e = lane + 32 * (half * 4 + j);
                    {
                        const float4 h = Hs[0][e];
                        s0 += w[j].x * h.x + w[j].y * h.y + w[j].z * h.z + w[j].w * h.w;
                    }
                    if (m > 1) {
                        const float4 h = Hs[1][e];
                        s1 += w[j].x * h.x + w[j].y * h.y + w[j].z * h.z + w[j].w * h.w;
                    }
                    if (m > 2) {
                        const float4 h = Hs[2][e];
                        s2 += w[j].x * h.x + w[j].y * h.y + w[j].z * h.z + w[j].w * h.w;
                    }
                    if (m > 3) {
                        const float4 h = Hs[3][e];
                        s3 += w[j].x * h.x + w[j].y * h.y + w[j].z * h.z + w[j].w * h.w;
                    }
                }
            }

            #pragma unroll
            for (int sft = 16; sft; sft >>= 1) {
                s0 += __shfl_xor_sync(0xffffffffu, s0, sft);
                s1 += __shfl_xor_sync(0xffffffffu, s1, sft);
                s2 += __shfl_xor_sync(0xffffffffu, s2, sft);
                s3 += __shfl_xor_sync(0xffffffffu, s3, sft);
            }
            if (lane == 0) {
                __stcs(&out[(size_t)toks[0] * VOCAB + cur_vid], s0);
                if (m > 1) __stcs(&out[(size_t)toks[1] * VOCAB + cur_vid], s1);
                if (m > 2) __stcs(&out[(size_t)toks[2] * VOCAB + cur_vid], s2);
                if (m > 3) __stcs(&out[(size_t)toks[3] * VOCAB + cur_vid], s3);
            }
        }
        __syncthreads();
    }
}

// ---------------------------------------------------------------------------
extern "C" void kernel_launch(void* const* d_in, const int* in_sizes, int n_in,
                              void* d_out, int out_size) {
    const float* H   = (const float*)d_in[0];   // (128, 1024)
    const float* W   = (const float*)d_in[1];   // (131072, 1024)
    const float* C   = (const float*)d_in[2];   // (512, 1024)
    const int*   ord = (const int*)d_in[3];     // (131072,)
    float* out = (float*)d_out;

    const int n4 = out_size / 4;
    scores_fill_kernel<<<dim3(NUM_T / 4, NC / 8), 256>>>(H, C, (float4*)out, n4);
    topk_kernel<<<NUM_T / 4, 128>>>();
    logits_kernel<<<NC * NCHUNK, 256>>>(H, W, ord, out);
}